// round 16
// baseline (speedup 1.0000x reference)
#include <cuda_runtime.h>
#include <cuda_fp16.h>
#include <cstddef>
#include <cstdint>

#define HD   512
#define VOC  32000
#define TT1  128
#define TT2  64
#define NB   32
#define H3   1536
#define BHD  (NB*HD)
#define YSZ  ((size_t)TT2*NB*VOC)
#define HF_OFF YSZ
#define LS_OFF (YSZ + (size_t)2*BHD)

typedef unsigned int uint_t;
typedef unsigned long long u64_t;

// ---------------- scratch (device globals; no runtime alloc) ----------------
__device__ float g_X  [TT2*NB*HD];
__device__ float g_q  [TT2*NB*HD];
__device__ float g_ep [TT1*NB*HD];
__device__ float g_sc [TT2*TT1*NB];
__device__ float g_av [TT2*NB*HD];
__device__ float g_gi0[TT2*NB*H3];
__device__ float g_ys [TT2*NB*HD];
__device__ float g_h0c[2*BHD];
__device__ float g_h1c[2*BHD];

// fp16 operands
__device__ __align__(16) __half h_ench [(size_t)TT1*NB * 1024];  // A2: [hi|lo]
__device__ __align__(16) __half h_Wxh  [512 * 1024];             // B2: [hi|hi]
__device__ __align__(16) __half h_Weh  [512 * 1024];             // B2
__device__ __align__(16) __half h_Xh   [(size_t)TT2*NB * 1024];  // A2
__device__ __align__(16) __half h_Xavh [(size_t)TT2*NB * 2048];  // A2 of [X|av]
__device__ __align__(16) __half h_Wih0h[(size_t)H3 * 2048];      // B2
__device__ __align__(16) __half h_oWh  [(size_t)VOC * 512];      // 1-term
__device__ __align__(16) __half h_ysh  [(size_t)TT2*NB * 512];   // 1-term

// split grid-barrier counters (8 counters, 128B apart; monotonic per launch)
__device__ unsigned g_bc8[8*32];

__device__ __forceinline__ int CH(int b, int k){ return ((k>>2)<<7) + (b<<2) + (k&3); }

__device__ __forceinline__ float fast_tanh(float x){
    float e = __expf(2.f*x);
    return 1.f - __fdividef(2.f, e + 1.f);
}
__device__ __forceinline__ float fast_sig(float x){
    return __fdividef(1.f, 1.f + __expf(-x));
}

// ---------------- barrier counter zero (tiny) ----------------
__global__ void k_zero()
{
    if (threadIdx.x < 8) g_bc8[threadIdx.x*32] = 0;
}

// ---------------- embed + state init + barrier reset ----------------
__global__ __launch_bounds__(256) void k_embed(const int* __restrict__ tok,
                                               const float* __restrict__ emb,
                                               const float* __restrict__ state)
{
    int i = blockIdx.x*256 + threadIdx.x;
    if (i < 8) g_bc8[i*32] = 0;
    if (i < TT2*NB*HD){
        int row = i >> 9;
        int h   = i & (HD-1);
        g_X[i] = emb[(size_t)tok[row]*HD + h];
    }
    if (i < 2*BHD){
        int l = (i >= BHD);
        int r = i & (BHD-1);
        int b = r >> 9, h = r & (HD-1);
        float v = state[i];
        if (l == 0) g_h0c[CH(b,h)] = v;
        else        g_h1c[CH(b,h)] = v;
    }
}

// ---------------- fp32 -> fp16 split conversion ----------------
__device__ __forceinline__ uint_t packh(__half a, __half b){
    return ((uint_t)__half_as_ushort(b) << 16) | (uint_t)__half_as_ushort(a);
}
__global__ void k_cath(const float* __restrict__ src, int src_ld, int Ksrc,
                       __half* __restrict__ dst, int dst_ld,
                       int off0, int off1, int mode)
{
    int row = blockIdx.x;
    for (int k = threadIdx.x*4; k < Ksrc; k += blockDim.x*4){
        float4 v = *reinterpret_cast<const float4*>(src + (size_t)row*src_ld + k);
        __half h0 = __float2half_rn(v.x), h1 = __float2half_rn(v.y);
        __half h2 = __float2half_rn(v.z), h3 = __float2half_rn(v.w);
        uint2 hv = make_uint2(packh(h0,h1), packh(h2,h3));
        *reinterpret_cast<uint2*>(dst + (size_t)row*dst_ld + off0 + k) = hv;
        if (mode == 0){
            __half l0 = __float2half_rn(v.x - __half2float(h0));
            __half l1 = __float2half_rn(v.y - __half2float(h1));
            __half l2 = __float2half_rn(v.z - __half2float(h2));
            __half l3 = __float2half_rn(v.w - __half2float(h3));
            uint2 lv = make_uint2(packh(l0,l1), packh(l2,l3));
            *reinterpret_cast<uint2*>(dst + (size_t)row*dst_ld + off1 + k) = lv;
        } else if (mode == 1){
            *reinterpret_cast<uint2*>(dst + (size_t)row*dst_ld + off1 + k) = hv;
        }
    }
}

// ---------------- fp16 GEMM (R12: cp.async 2-stage, stride-20 smem) ---------
__device__ __forceinline__ uint32_t s2u(const void* p){
    uint32_t a;
    asm("{ .reg .u64 t; cvta.to.shared.u64 t, %1; cvt.u32.u64 %0, t; }" : "=r"(a) : "l"(p));
    return a;
}
__device__ __forceinline__ void cpa16(uint32_t s, const void* g){
    asm volatile("cp.async.cg.shared.global [%0], [%1], 16;" :: "r"(s), "l"(g));
}
__device__ __forceinline__ void mma16f(float* d, const uint_t* a, uint_t b0, uint_t b1){
    asm volatile("mma.sync.aligned.m16n8k16.row.col.f32.f16.f16.f32 "
        "{%0,%1,%2,%3}, {%4,%5,%6,%7}, {%8,%9}, {%0,%1,%2,%3};\n"
        : "+f"(d[0]), "+f"(d[1]), "+f"(d[2]), "+f"(d[3])
        : "r"(a[0]), "r"(a[1]), "r"(a[2]), "r"(a[3]), "r"(b0), "r"(b1));
}
#define SROW 20

__global__ __launch_bounds__(256, 2) void k_gemmh(
    const uint_t* __restrict__ A, int lda,
    const uint_t* __restrict__ B, int ldb,
    const float* __restrict__ bias,
    float* __restrict__ C, int ldc, int K)
{
    __shared__ __align__(16) uint_t sA[2][128*SROW], sB[2][128*SROW];
    const int m0 = blockIdx.y * 128;
    const int n0 = blockIdx.x * 128;
    const int tid = threadIdx.x, lane = tid & 31, warp = tid >> 5;
    const int wm = (warp & 1) * 64;
    const int wn = (warp >> 1) * 32;
    const int g  = lane >> 2, tg = lane & 3;

    const int nch = K >> 5;
    const int lrow = tid >> 1;
    const int lp   = (tid & 1) * 8;

    float acc[4][4][4];
    #pragma unroll
    for (int i=0;i<4;i++)
        #pragma unroll
        for (int j=0;j<4;j++){ acc[i][j][0]=0.f; acc[i][j][1]=0.f; acc[i][j][2]=0.f; acc[i][j][3]=0.f; }

    auto load_stage = [&](int c){
        const int st  = c & 1;
        const int khu = c * 16;
        const uint_t* ga = A + (size_t)(m0 + lrow)*lda + khu + lp;
        const uint_t* gb = B + (size_t)(n0 + lrow)*ldb + khu + lp;
        uint32_t da = s2u(&sA[st][lrow*SROW + lp]);
        uint32_t db = s2u(&sB[st][lrow*SROW + lp]);
        cpa16(da,      ga);
        cpa16(da + 16, ga + 4);
        cpa16(db,      gb);
        cpa16(db + 16, gb + 4);
        asm volatile("cp.async.commit_group;" ::: "memory");
    };

    load_stage(0);
    for (int c = 0; c < nch; c++){
        asm volatile("cp.async.wait_group 0;" ::: "memory");
        __syncthreads();
        if (c + 1 < nch) load_stage(c + 1);
        const int st = c & 1;
        #pragma unroll
        for (int h2=0; h2<2; h2++){
            const int kb2 = h2*8;
            const int P0 = kb2 + tg;
            const int P1 = kb2 + tg + 4;
            #pragma unroll
            for (int mp=0; mp<2; mp++){
                uint_t ah[2][4];
                #pragma unroll
                for (int q=0;q<2;q++){
                    int r0 = wm + (mp*2+q)*16 + g;
                    ah[q][0]=sA[st][r0*SROW + P0];     ah[q][1]=sA[st][(r0+8)*SROW + P0];
                    ah[q][2]=sA[st][r0*SROW + P1];     ah[q][3]=sA[st][(r0+8)*SROW + P1];
                }
                #pragma unroll
                for (int ns=0; ns<4; ns++){
                    int col = wn + ns*8 + g;
                    uint_t b0 = sB[st][col*SROW + P0];
                    uint_t b1 = sB[st][col*SROW + P1];
                    #pragma unroll
                    for (int q=0;q<2;q++)
                        mma16f(acc[mp*2+q][ns], ah[q], b0, b1);
                }
            }
        }
        __syncthreads();
    }
    #pragma unroll
    for (int ms=0; ms<4; ms++){
        #pragma unroll
        for (int ns=0; ns<4; ns++){
            int r0  = m0 + wm + ms*16 + g;
            int col = n0 + wn + ns*8 + tg*2;
            float b0v = 0.f, b1v = 0.f;
            if (bias){ b0v = bias[col]; b1v = bias[col+1]; }
            float2 v0 = make_float2(acc[ms][ns][0]+b0v, acc[ms][ns][1]+b1v);
            float2 v1 = make_float2(acc[ms][ns][2]+b0v, acc[ms][ns][3]+b1v);
            *reinterpret_cast<float2*>(C + (size_t)r0*ldc + col)     = v0;
            *reinterpret_cast<float2*>(C + (size_t)(r0+8)*ldc + col) = v1;
        }
    }
}

// ---------------- attention logits + softmax ----------------
__global__ __launch_bounds__(256) void k_att_scores(const float* __restrict__ va,
                                                    float* __restrict__ dout)
{
    __shared__ float q8[8*HD];
    __shared__ float vsm[HD];
    __shared__ float esm[8*TT1];
    const int b   = blockIdx.y;
    const int t2b = blockIdx.x * 8;
    const int tid = threadIdx.x, lane = tid & 31, w = tid >> 5;

    for (int i = tid; i < 8*HD; i += 256){
        int t2i = i >> 9, h = i & (HD-1);
        q8[i] = g_q[((size_t)(t2b + t2i)*NB + b)*HD + h];
    }
    for (int i = tid; i < HD; i += 256) vsm[i] = va[i];
    __syncthreads();

    for (int t1 = w; t1 < TT1; t1 += 8){
        const float* ep = g_ep + ((size_t)t1*NB + b)*HD;
        float accv[8];
        #pragma unroll
        for (int i=0;i<8;i++) accv[i] = 0.f;
        for (int h = lane; h < HD; h += 32){
            float e  = ep[h];
            float vv = vsm[h];
            #pragma unroll
            for (int i=0;i<8;i++) accv[i] += vv * fast_tanh(q8[i*HD + h] + e);
        }
        #pragma unroll
        for (int i=0;i<8;i++){
            float s = accv[i];
            #pragma unroll
            for (int o=16;o;o>>=1) s += __shfl_xor_sync(0xffffffffu, s, o);
            if (lane == 0) esm[i*TT1 + t1] = s;
        }
    }
    __syncthreads();

    {
        float v[4];
        #pragma unroll
        for (int i=0;i<4;i++) v[i] = esm[w*TT1 + lane + 32*i];
        float m = fmaxf(fmaxf(v[0],v[1]), fmaxf(v[2],v[3]));
        #pragma unroll
        for (int o=16;o;o>>=1) m = fmaxf(m, __shfl_xor_sync(0xffffffffu, m, o));
        float s = 0.f;
        #pragma unroll
        for (int i=0;i<4;i++){ v[i] = __expf(v[i]-m); s += v[i]; }
        #pragma unroll
        for (int o=16;o;o>>=1) s += __shfl_xor_sync(0xffffffffu, s, o);
        float inv = __fdividef(1.f, s);
        int t2 = t2b + w;
        #pragma unroll
        for (int i=0;i<4;i++){
            int t1 = lane + 32*i;
            float sc = v[i]*inv;
            g_sc[((size_t)t2*TT1 + t1)*NB + b] = sc;
            if (t2 == TT2-1) dout[LS_OFF + (size_t)t1*NB + b] = sc;
        }
    }
}

// ---------------- attention values ----------------
__global__ __launch_bounds__(256) void k_attv(const float* __restrict__ enc)
{
    __shared__ float sst[TT1*32];
    const int b   = blockIdx.x;
    const int t2o = blockIdx.y * 32;
    const int h   = blockIdx.z * 256 + threadIdx.x;
    for (int i = threadIdx.x; i < 32*TT1; i += 256){
        int t1 = i >> 5, i2 = i & 31;
        sst[t1*32 + i2] = g_sc[((size_t)(t2o + i2)*TT1 + t1)*NB + b];
    }
    __syncthreads();
    float acc[32];
    #pragma unroll
    for (int i=0;i<32;i++) acc[i] = 0.f;
    for (int t1 = 0; t1 < TT1; t1++){
        float ev = enc[((size_t)t1*NB + b)*HD + h];
        #pragma unroll
        for (int i=0;i<32;i++) acc[i] += ev * sst[t1*32 + i];
    }
    #pragma unroll
    for (int i=0;i<32;i++)
        g_av[((size_t)(t2o+i)*NB + b)*HD + h] = acc[i];
}

// ---------------- persistent recurrence v4: f32x2 FFMA + split barrier ------
#define NBLK2 128

__device__ __forceinline__ void ffma2(u64_t& d, u64_t a, u64_t b){
    asm("fma.rn.f32x2 %0, %1, %2, %0;" : "+l"(d) : "l"(a), "l"(b));
}
__device__ __forceinline__ float2 up2(u64_t v){
    float2 r; asm("mov.b64 {%0,%1}, %2;" : "=f"(r.x), "=f"(r.y) : "l"(v)); return r;
}

__device__ __forceinline__ void dotsm(const float* __restrict__ W, int j,
                                      const float* __restrict__ shb, int b,
                                      float& s0, float& s1, float& s2)
{
    const ulonglong2* w0 = reinterpret_cast<const ulonglong2*>(W + (size_t) j        *HD);
    const ulonglong2* w1 = reinterpret_cast<const ulonglong2*>(W + (size_t)(j+ 512)  *HD);
    const ulonglong2* w2 = reinterpret_cast<const ulonglong2*>(W + (size_t)(j+1024)  *HD);
    u64_t a0 = 0ull, a1 = 0ull, a2 = 0ull;   // packed (+0,+0)
    #pragma unroll 8
    for (int kk = 0; kk < HD; kk += 4){
        ulonglong2 hv = *reinterpret_cast<const ulonglong2*>(shb + ((kk>>2)<<7) + (b<<2));
        ulonglong2 x = w0[kk>>2], y = w1[kk>>2], z = w2[kk>>2];
        ffma2(a0, x.x, hv.x);  ffma2(a0, x.y, hv.y);
        ffma2(a1, y.x, hv.x);  ffma2(a1, y.y, hv.y);
        ffma2(a2, z.x, hv.x);  ffma2(a2, z.y, hv.y);
    }
    float2 f0 = up2(a0), f1 = up2(a1), f2 = up2(a2);
    s0 = f0.x + f0.y;  s1 = f1.x + f1.y;  s2 = f2.x + f2.y;
}

__global__ __launch_bounds__(384, 1) void k_rec(
    const float* __restrict__ W_hh0, const float* __restrict__ b_hh0,
    const float* __restrict__ W_ih1, const float* __restrict__ b_ih1,
    const float* __restrict__ W_hh1, const float* __restrict__ b_hh1,
    int tlim)
{
    extern __shared__ float sh[];          // 2*BHD floats = 128 KB
    __shared__ float sm[12][3][32];
    const int blk  = blockIdx.x;
    const int tid  = threadIdx.x;
    const int warp = tid >> 5;
    const int b    = tid & 31;
    const int slot = blk*12 + warp;
    const bool g0u = (slot >= 1024);
    const bool blk_has_g1 = (blk*12 < 1024);
    unsigned* myc = &g_bc8[(blk & 7)*32];

    for (int t = 0; t <= tlim; t++){
        {
            const float* sp0 = g_h0c + (t&1)*BHD;
            for (int i = tid*4; i < BHD; i += 1536)
                *reinterpret_cast<float4*>(sh + i) =
                    __ldcg(reinterpret_cast<const float4*>(sp0 + i));
            if (blk_has_g1 && t >= 1){
                const float* sp1 = g_h1c + ((t-1)&1)*BHD;
                for (int i = tid*4; i < BHD; i += 1536)
                    *reinterpret_cast<float4*>(sh + BHD + i) =
                        __ldcg(reinterpret_cast<const float4*>(sp1 + i));
            }
        }
        __syncthreads();

        float s0=0.f, s1=0.f, s2=0.f;
        int j = 0, mat = 0;
        bool act = false;
        if (g0u){
            if (t < TT2){
                act = true;  j = slot - 1024;
                dotsm(W_hh0, j, sh, b, s0, s1, s2);
            }
        } else {
            if (t >= 1){
                act = true;  j = slot >> 1;  mat = slot & 1;
                dotsm(mat ? W_hh1 : W_ih1, j, sh + mat*BHD, b, s0, s1, s2);
            }
        }
        if (!g0u){ sm[warp][0][b] = s0; sm[warp][1][b] = s1; sm[warp][2][b] = s2; }
        __syncthreads();

        if (act){
            if (g0u){
                const float* gi = g_gi0 + ((size_t)t*NB + b)*H3;
                float r = fast_sig (gi[j      ] + s0 + b_hh0[j      ]);
                float z = fast_sig (gi[j+ 512] + s1 + b_hh0[j+ 512]);
                float n = fast_tanh(gi[j+1024] + r*(s2 + b_hh0[j+1024]));
                float hold = sh[CH(b,j)];
                __stcg(&g_h0c[(1-(t&1))*BHD + CH(b,j)], (1.f-z)*n + z*hold);
            } else if (mat == 0){
                const int s = t - 1;
                float xr = s0 + b_ih1[j      ];
                float xz = s1 + b_ih1[j+ 512];
                float xn = s2 + b_ih1[j+1024];
                float hr = sm[warp+1][0][b] + b_hh1[j      ];
                float hz = sm[warp+1][1][b] + b_hh1[j+ 512];
                float hn = sm[warp+1][2][b] + b_hh1[j+1024];
                float r = fast_sig(xr + hr);
                float z = fast_sig(xz + hz);
                float n = fast_tanh(xn + r*hn);
                float h1old = sh[BHD + CH(b,j)];
                float hnew = (1.f-z)*n + z*h1old;
                __stcg(&g_h1c[(t&1)*BHD + CH(b,j)], hnew);
                g_ys[((size_t)s*NB + b)*HD + j] = hnew;
            }
        }
        if (t == tlim) break;
        // ---- grid barrier: 8 split counters (release-add, acquire-poll) ----
        __syncthreads();
        if (tid == 0){
            unsigned old;
            asm volatile("atom.release.gpu.global.add.u32 %0, [%1], %2;"
                         : "=r"(old) : "l"(myc), "r"(1u) : "memory");
            const unsigned tgt = (unsigned)(t + 1) * (NBLK2/8);
            bool ok;
            do {
                ok = true;
                #pragma unroll
                for (int c = 0; c < 8; c++){
                    unsigned cur;
                    asm volatile("ld.acquire.gpu.global.u32 %0, [%1];"
                                 : "=r"(cur) : "l"(&g_bc8[c*32]) : "memory");
                    ok &= (cur >= tgt);
                }
                if (!ok) __nanosleep(32);
            } while (!ok);
        }
        __syncthreads();
    }
}

// ---------------- final state copy ----------------
__global__ __launch_bounds__(256) void k_fin(float* __restrict__ dout)
{
    int i = blockIdx.x*256 + threadIdx.x;
    if (i >= 2*BHD) return;
    int l = (i >= BHD);
    int r = i & (BHD-1);
    int b = r >> 9, h = r & (HD-1);
    float v = l ? g_h1c[CH(b,h)] : g_h0c[CH(b,h)];
    dout[HF_OFF + i] = v;
}

extern "C" void kernel_launch(void* const* d_in, const int* in_sizes, int n_in,
                              void* d_out, int out_size)
{
    const int*   tok   = (const int*)  d_in[0];
    const float* state = (const float*)d_in[1];
    const float* enc   = (const float*)d_in[2];
    const float* emb   = (const float*)d_in[3];
    const float* wa_W  = (const float*)d_in[4];
    const float* wa_b  = (const float*)d_in[5];
    const float* va_W  = (const float*)d_in[6];
    const float* W_ih0 = (const float*)d_in[7];
    const float* W_hh0 = (const float*)d_in[8];
    const float* b_ih0 = (const float*)d_in[9];
    const float* b_hh0 = (const float*)d_in[10];
    const float* W_ih1 = (const float*)d_in[11];
    const float* W_hh1 = (const float*)d_in[12];
    const float* b_ih1 = (const float*)d_in[13];
    const float* b_hh1 = (const float*)d_in[14];
    const float* out_W = (const float*)d_in[15];
    const float* out_b = (const float*)d_in[16];
    float* dout = (float*)d_out;

    float *pX, *pep, *pq, *pav, *pgi0, *pys;
    __half *pench, *pWxh, *pWeh, *pXh, *pXavh, *pWih0h, *poWh, *pysh;
    cudaGetSymbolAddress((void**)&pX,     g_X);
    cudaGetSymbolAddress((void**)&pep,    g_ep);
    cudaGetSymbolAddress((void**)&pq,     g_q);
    cudaGetSymbolAddress((void**)&pav,    g_av);
    cudaGetSymbolAddress((void**)&pgi0,   g_gi0);
    cudaGetSymbolAddress((void**)&pys,    g_ys);
    cudaGetSymbolAddress((void**)&pench,  h_ench);
    cudaGetSymbolAddress((void**)&pWxh,   h_Wxh);
    cudaGetSymbolAddress((void**)&pWeh,   h_Weh);
    cudaGetSymbolAddress((void**)&pXh,    h_Xh);
    cudaGetSymbolAddress((void**)&pXavh,  h_Xavh);
    cudaGetSymbolAddress((void**)&pWih0h, h_Wih0h);
    cudaGetSymbolAddress((void**)&poWh,   h_oWh);
    cudaGetSymbolAddress((void**)&pysh,   h_ysh);

    cudaFuncSetAttribute(k_rec, cudaFuncAttributeMaxDynamicSharedMemorySize, 2*BHD*4);

    // --- launch order: #4 is a 4-step k_rec PROBE (ncu -s5 -c1 lands there).
    //     The probe runs BEFORE k_embed, which re-initializes everything the
    //     probe touches (h state, barrier counters); probe output is ignored.
    // 1. zero barrier counters (for the probe)
    k_zero<<<1, 32>>>();
    // 2-3. conversions needed by enc_proj
    k_cath<<<TT1*NB, 128>>>(enc,        HD, HD, pench, 1024, 0, 512, 0);   // A2
    k_cath<<<512,    128>>>(wa_W + HD, 2*HD, HD, pWeh, 1024, 0, 512, 1);   // B2
    // 4. k_rec PROBE: 4 steps, representative work, profiled
    k_rec<<<NBLK2, 384, 2*BHD*4>>>(W_hh0, b_hh0, W_ih1, b_ih1, W_hh1, b_hh1, 4);
    // 5. embed + state init + barrier counter reset (undoes the probe)
    k_embed<<<(TT2*NB*HD + 255)/256, 256>>>(tok, emb, state);
    // 6-7. conversions for q
    k_cath<<<512,    128>>>(wa_W,      2*HD, HD, pWxh, 1024, 0, 512, 1);   // B2
    k_cath<<<TT2*NB, 128>>>(pX,         HD, HD, pXh,  1024, 0, 512, 0);    // A2
    // 8. enc_proj = enc @ We^T + wa_b   (M=4096, N=512, K'=1024)
    k_gemmh<<<dim3(HD/128, (TT1*NB)/128), 256>>>((const uint_t*)pench, 512,
        (const uint_t*)pWeh, 512, wa_b, pep, HD, 1024);
    // 9. q = X @ Wx^T                   (M=2048, N=512, K'=1024)
    k_gemmh<<<dim3(HD/128, (TT2*NB)/128), 256>>>((const uint_t*)pXh, 512,
        (const uint_t*)pWxh, 512, nullptr, pq, HD, 1024);

    // remaining conversions
    k_cath<<<H3,     256>>>(W_ih0, 2*HD, 2*HD, pWih0h, 2048, 0, 1024, 1);  // B2
    k_cath<<<VOC,    128>>>(out_W,   HD,   HD, poWh,    512, 0, 0, 2);     // 1-term
    k_cath<<<TT2*NB, 128>>>(pX,      HD,   HD, pXavh,  2048, 0, 1024, 0);  // A2 (X part)

    // attention
    k_att_scores<<<dim3(TT2/8, NB), 256>>>(va_W, dout);
    k_attv<<<dim3(NB, TT2/32, HD/256), 256>>>(enc);
    k_cath<<<TT2*NB, 128>>>(pav, HD, HD, pXavh, 2048, 512, 1536, 0);       // A2 (av part)

    // gi0 = [X, att_v] @ W_ih0^T + b_ih0   (M=2048, N=1536, K'=2048)
    k_gemmh<<<dim3(H3/128, (TT2*NB)/128), 256>>>((const uint_t*)pXavh, 1024,
        (const uint_t*)pWih0h, 1024, b_ih0, pgi0, H3, 2048);

    // recurrence (real run)
    k_rec<<<NBLK2, 384, 2*BHD*4>>>(W_hh0, b_hh0, W_ih1, b_ih1, W_hh1, b_hh1, TT2);

    // y = ys @ out_W^T + out_b   (M=2048, N=32000, K=512, 1-term fp16)
    k_cath<<<TT2*NB, 128>>>(pys, HD, HD, pysh, 512, 0, 0, 2);
    k_gemmh<<<dim3(VOC/128, (TT2*NB)/128), 256>>>((const uint_t*)pysh, 256,
        (const uint_t*)poWh, 256, out_b, dout, VOC, 512);

    // final hidden states
    k_fin<<<(2*BHD + 255)/256, 256>>>(dout);
    (void)in_sizes; (void)n_in; (void)out_size;
}

// round 17
// speedup vs baseline: 1.0695x; 1.0695x over previous
#include <cuda_runtime.h>
#include <cuda_fp16.h>
#include <cstddef>
#include <cstdint>

#define HD   512
#define VOC  32000
#define TT1  128
#define TT2  64
#define NB   32
#define H3   1536
#define BHD  (NB*HD)
#define YSZ  ((size_t)TT2*NB*VOC)
#define HF_OFF YSZ
#define LS_OFF (YSZ + (size_t)2*BHD)

typedef unsigned int uint_t;

// ---------------- scratch (device globals; no runtime alloc) ----------------
__device__ float g_X  [TT2*NB*HD];
__device__ float g_q  [TT2*NB*HD];
__device__ float g_ep [TT1*NB*HD];
__device__ float g_sc [TT2*TT1*NB];
__device__ float g_av [TT2*NB*HD];
__device__ float g_gi0[TT2*NB*H3];
__device__ float g_ys [TT2*NB*HD];
__device__ float g_h0c[2*BHD];
__device__ float g_h1c[2*BHD];

// fp16 operands
__device__ __align__(16) __half h_ench [(size_t)TT1*NB * 1024];  // A2: [hi|lo]
__device__ __align__(16) __half h_Wxh  [512 * 1024];             // B2: [hi|hi]
__device__ __align__(16) __half h_Weh  [512 * 1024];             // B2
__device__ __align__(16) __half h_Xh   [(size_t)TT2*NB * 1024];  // A2
__device__ __align__(16) __half h_Xavh [(size_t)TT2*NB * 2048];  // A2 of [X|av]
__device__ __align__(16) __half h_Wih0h[(size_t)H3 * 2048];      // B2
__device__ __align__(16) __half h_oWh  [(size_t)VOC * 512];      // 1-term
__device__ __align__(16) __half h_ysh  [(size_t)TT2*NB * 512];   // 1-term

// two-level grid barrier (monotonic per launch; reset by k_embed)
__device__ unsigned g_bc8[8*32];
__device__ unsigned g_master;

__device__ __forceinline__ int CH(int b, int k){ return ((k>>2)<<7) + (b<<2) + (k&3); }

__device__ __forceinline__ float fast_tanh(float x){
    float e = __expf(2.f*x);
    return 1.f - __fdividef(2.f, e + 1.f);
}
__device__ __forceinline__ float fast_sig(float x){
    return __fdividef(1.f, 1.f + __expf(-x));
}

// ---------------- embed + state init + barrier reset ----------------
__global__ __launch_bounds__(256) void k_embed(const int* __restrict__ tok,
                                               const float* __restrict__ emb,
                                               const float* __restrict__ state)
{
    int i = blockIdx.x*256 + threadIdx.x;
    if (i < 8) g_bc8[i*32] = 0;
    if (i == 8) g_master = 0;
    if (i < TT2*NB*HD){
        int row = i >> 9;
        int h   = i & (HD-1);
        g_X[i] = emb[(size_t)tok[row]*HD + h];
    }
    if (i < 2*BHD){
        int l = (i >= BHD);
        int r = i & (BHD-1);
        int b = r >> 9, h = r & (HD-1);
        float v = state[i];
        if (l == 0) g_h0c[CH(b,h)] = v;
        else        g_h1c[CH(b,h)] = v;
    }
}

// ---------------- fp32 -> fp16 split conversion ----------------
__device__ __forceinline__ uint_t packh(__half a, __half b){
    return ((uint_t)__half_as_ushort(b) << 16) | (uint_t)__half_as_ushort(a);
}
__global__ void k_cath(const float* __restrict__ src, int src_ld, int Ksrc,
                       __half* __restrict__ dst, int dst_ld,
                       int off0, int off1, int mode)
{
    int row = blockIdx.x;
    for (int k = threadIdx.x*4; k < Ksrc; k += blockDim.x*4){
        float4 v = *reinterpret_cast<const float4*>(src + (size_t)row*src_ld + k);
        __half h0 = __float2half_rn(v.x), h1 = __float2half_rn(v.y);
        __half h2 = __float2half_rn(v.z), h3 = __float2half_rn(v.w);
        uint2 hv = make_uint2(packh(h0,h1), packh(h2,h3));
        *reinterpret_cast<uint2*>(dst + (size_t)row*dst_ld + off0 + k) = hv;
        if (mode == 0){
            __half l0 = __float2half_rn(v.x - __half2float(h0));
            __half l1 = __float2half_rn(v.y - __half2float(h1));
            __half l2 = __float2half_rn(v.z - __half2float(h2));
            __half l3 = __float2half_rn(v.w - __half2float(h3));
            uint2 lv = make_uint2(packh(l0,l1), packh(l2,l3));
            *reinterpret_cast<uint2*>(dst + (size_t)row*dst_ld + off1 + k) = lv;
        } else if (mode == 1){
            *reinterpret_cast<uint2*>(dst + (size_t)row*dst_ld + off1 + k) = hv;
        }
    }
}

// ---------------- shared helpers ----------------
__device__ __forceinline__ uint32_t s2u(const void* p){
    uint32_t a;
    asm("{ .reg .u64 t; cvta.to.shared.u64 t, %1; cvt.u32.u64 %0, t; }" : "=r"(a) : "l"(p));
    return a;
}
__device__ __forceinline__ void cpa16(uint32_t s, const void* g){
    asm volatile("cp.async.cg.shared.global [%0], [%1], 16;" :: "r"(s), "l"(g));
}

// ---------------- fp16 GEMM (R12: cp.async 2-stage, stride-20 smem) ---------
__device__ __forceinline__ void mma16f(float* d, const uint_t* a, uint_t b0, uint_t b1){
    asm volatile("mma.sync.aligned.m16n8k16.row.col.f32.f16.f16.f32 "
        "{%0,%1,%2,%3}, {%4,%5,%6,%7}, {%8,%9}, {%0,%1,%2,%3};\n"
        : "+f"(d[0]), "+f"(d[1]), "+f"(d[2]), "+f"(d[3])
        : "r"(a[0]), "r"(a[1]), "r"(a[2]), "r"(a[3]), "r"(b0), "r"(b1));
}
#define SROW 20

__global__ __launch_bounds__(256, 2) void k_gemmh(
    const uint_t* __restrict__ A, int lda,
    const uint_t* __restrict__ B, int ldb,
    const float* __restrict__ bias,
    float* __restrict__ C, int ldc, int K)
{
    __shared__ __align__(16) uint_t sA[2][128*SROW], sB[2][128*SROW];
    const int m0 = blockIdx.y * 128;
    const int n0 = blockIdx.x * 128;
    const int tid = threadIdx.x, lane = tid & 31, warp = tid >> 5;
    const int wm = (warp & 1) * 64;
    const int wn = (warp >> 1) * 32;
    const int g  = lane >> 2, tg = lane & 3;

    const int nch = K >> 5;
    const int lrow = tid >> 1;
    const int lp   = (tid & 1) * 8;

    float acc[4][4][4];
    #pragma unroll
    for (int i=0;i<4;i++)
        #pragma unroll
        for (int j=0;j<4;j++){ acc[i][j][0]=0.f; acc[i][j][1]=0.f; acc[i][j][2]=0.f; acc[i][j][3]=0.f; }

    auto load_stage = [&](int c){
        const int st  = c & 1;
        const int khu = c * 16;
        const uint_t* ga = A + (size_t)(m0 + lrow)*lda + khu + lp;
        const uint_t* gb = B + (size_t)(n0 + lrow)*ldb + khu + lp;
        uint32_t da = s2u(&sA[st][lrow*SROW + lp]);
        uint32_t db = s2u(&sB[st][lrow*SROW + lp]);
        cpa16(da,      ga);
        cpa16(da + 16, ga + 4);
        cpa16(db,      gb);
        cpa16(db + 16, gb + 4);
        asm volatile("cp.async.commit_group;" ::: "memory");
    };

    load_stage(0);
    for (int c = 0; c < nch; c++){
        asm volatile("cp.async.wait_group 0;" ::: "memory");
        __syncthreads();
        if (c + 1 < nch) load_stage(c + 1);
        const int st = c & 1;
        #pragma unroll
        for (int h2=0; h2<2; h2++){
            const int kb2 = h2*8;
            const int P0 = kb2 + tg;
            const int P1 = kb2 + tg + 4;
            #pragma unroll
            for (int mp=0; mp<2; mp++){
                uint_t ah[2][4];
                #pragma unroll
                for (int q=0;q<2;q++){
                    int r0 = wm + (mp*2+q)*16 + g;
                    ah[q][0]=sA[st][r0*SROW + P0];     ah[q][1]=sA[st][(r0+8)*SROW + P0];
                    ah[q][2]=sA[st][r0*SROW + P1];     ah[q][3]=sA[st][(r0+8)*SROW + P1];
                }
                #pragma unroll
                for (int ns=0; ns<4; ns++){
                    int col = wn + ns*8 + g;
                    uint_t b0 = sB[st][col*SROW + P0];
                    uint_t b1 = sB[st][col*SROW + P1];
                    #pragma unroll
                    for (int q=0;q<2;q++)
                        mma16f(acc[mp*2+q][ns], ah[q], b0, b1);
                }
            }
        }
        __syncthreads();
    }
    #pragma unroll
    for (int ms=0; ms<4; ms++){
        #pragma unroll
        for (int ns=0; ns<4; ns++){
            int r0  = m0 + wm + ms*16 + g;
            int col = n0 + wn + ns*8 + tg*2;
            float b0v = 0.f, b1v = 0.f;
            if (bias){ b0v = bias[col]; b1v = bias[col+1]; }
            float2 v0 = make_float2(acc[ms][ns][0]+b0v, acc[ms][ns][1]+b1v);
            float2 v1 = make_float2(acc[ms][ns][2]+b0v, acc[ms][ns][3]+b1v);
            *reinterpret_cast<float2*>(C + (size_t)r0*ldc + col)     = v0;
            *reinterpret_cast<float2*>(C + (size_t)(r0+8)*ldc + col) = v1;
        }
    }
}

// ---------------- attention logits + softmax ----------------
__global__ __launch_bounds__(256) void k_att_scores(const float* __restrict__ va,
                                                    float* __restrict__ dout)
{
    __shared__ float q8[8*HD];
    __shared__ float vsm[HD];
    __shared__ float esm[8*TT1];
    const int b   = blockIdx.y;
    const int t2b = blockIdx.x * 8;
    const int tid = threadIdx.x, lane = tid & 31, w = tid >> 5;

    for (int i = tid; i < 8*HD; i += 256){
        int t2i = i >> 9, h = i & (HD-1);
        q8[i] = g_q[((size_t)(t2b + t2i)*NB + b)*HD + h];
    }
    for (int i = tid; i < HD; i += 256) vsm[i] = va[i];
    __syncthreads();

    for (int t1 = w; t1 < TT1; t1 += 8){
        const float* ep = g_ep + ((size_t)t1*NB + b)*HD;
        float accv[8];
        #pragma unroll
        for (int i=0;i<8;i++) accv[i] = 0.f;
        for (int h = lane; h < HD; h += 32){
            float e  = ep[h];
            float vv = vsm[h];
            #pragma unroll
            for (int i=0;i<8;i++) accv[i] += vv * fast_tanh(q8[i*HD + h] + e);
        }
        #pragma unroll
        for (int i=0;i<8;i++){
            float s = accv[i];
            #pragma unroll
            for (int o=16;o;o>>=1) s += __shfl_xor_sync(0xffffffffu, s, o);
            if (lane == 0) esm[i*TT1 + t1] = s;
        }
    }
    __syncthreads();

    {
        float v[4];
        #pragma unroll
        for (int i=0;i<4;i++) v[i] = esm[w*TT1 + lane + 32*i];
        float m = fmaxf(fmaxf(v[0],v[1]), fmaxf(v[2],v[3]));
        #pragma unroll
        for (int o=16;o;o>>=1) m = fmaxf(m, __shfl_xor_sync(0xffffffffu, m, o));
        float s = 0.f;
        #pragma unroll
        for (int i=0;i<4;i++){ v[i] = __expf(v[i]-m); s += v[i]; }
        #pragma unroll
        for (int o=16;o;o>>=1) s += __shfl_xor_sync(0xffffffffu, s, o);
        float inv = __fdividef(1.f, s);
        int t2 = t2b + w;
        #pragma unroll
        for (int i=0;i<4;i++){
            int t1 = lane + 32*i;
            float sc = v[i]*inv;
            g_sc[((size_t)t2*TT1 + t1)*NB + b] = sc;
            if (t2 == TT2-1) dout[LS_OFF + (size_t)t1*NB + b] = sc;
        }
    }
}

// ---------------- attention values ----------------
__global__ __launch_bounds__(256) void k_attv(const float* __restrict__ enc)
{
    __shared__ float sst[TT1*32];
    const int b   = blockIdx.x;
    const int t2o = blockIdx.y * 32;
    const int h   = blockIdx.z * 256 + threadIdx.x;
    for (int i = threadIdx.x; i < 32*TT1; i += 256){
        int t1 = i >> 5, i2 = i & 31;
        sst[t1*32 + i2] = g_sc[((size_t)(t2o + i2)*TT1 + t1)*NB + b];
    }
    __syncthreads();
    float acc[32];
    #pragma unroll
    for (int i=0;i<32;i++) acc[i] = 0.f;
    for (int t1 = 0; t1 < TT1; t1++){
        float ev = enc[((size_t)t1*NB + b)*HD + h];
        #pragma unroll
        for (int i=0;i<32;i++) acc[i] += ev * sst[t1*32 + i];
    }
    #pragma unroll
    for (int i=0;i<32;i++)
        g_av[((size_t)(t2o+i)*NB + b)*HD + h] = acc[i];
}

// ---------------- persistent recurrence v5: chunked cp.async + 2-level barrier
#define NBLK2 128

__device__ __forceinline__ void dotc(const float* __restrict__ W0,
                                     const float* __restrict__ W1,
                                     const float* __restrict__ W2,
                                     const float* __restrict__ shb, int b, int kb,
                                     float& s0, float& s1, float& s2)
{
    float a0=s0, a1=s1, a2=s2;
    #pragma unroll 8
    for (int kk = kb; kk < kb+128; kk += 4){
        float4 hv = *reinterpret_cast<const float4*>(shb + ((kk>>2)<<7) + (b<<2));
        float4 x = *reinterpret_cast<const float4*>(W0 + kk);
        float4 y = *reinterpret_cast<const float4*>(W1 + kk);
        float4 z = *reinterpret_cast<const float4*>(W2 + kk);
        a0 += x.x*hv.x + x.y*hv.y + x.z*hv.z + x.w*hv.w;
        a1 += y.x*hv.x + y.y*hv.y + y.z*hv.z + y.w*hv.w;
        a2 += z.x*hv.x + z.y*hv.y + z.z*hv.z + z.w*hv.w;
    }
    s0 = a0; s1 = a1; s2 = a2;
}

__global__ __launch_bounds__(384, 1) void k_rec(
    const float* __restrict__ W_hh0, const float* __restrict__ b_hh0,
    const float* __restrict__ W_ih1, const float* __restrict__ b_ih1,
    const float* __restrict__ W_hh1, const float* __restrict__ b_hh1)
{
    extern __shared__ float sh[];          // 2*BHD floats = 128 KB
    __shared__ float sm[12][3][32];
    const int blk  = blockIdx.x;
    const int tid  = threadIdx.x;
    const int warp = tid >> 5;
    const int b    = tid & 31;
    const int slot = blk*12 + warp;
    const bool g0u = (slot >= 1024);
    const bool has_g1 = (blk*12 < 1024);

    // fixed weight rows for this warp-unit
    int j, mat = 0;
    const float *W0, *W1, *W2;
    if (g0u){
        j = slot - 1024;
        W0 = W_hh0 + (size_t)j*HD; W1 = W_hh0 + (size_t)(j+512)*HD; W2 = W_hh0 + (size_t)(j+1024)*HD;
    } else {
        j = slot >> 1;  mat = slot & 1;
        const float* W = mat ? W_hh1 : W_ih1;
        W0 = W + (size_t)j*HD; W1 = W + (size_t)(j+512)*HD; W2 = W + (size_t)(j+1024)*HD;
    }
    const float* shb_my = sh + (g0u ? 0 : mat*BHD);
    unsigned* myc = &g_bc8[(blk & 7)*32];

    for (int t = 0; t <= TT2; t++){
        const float* sp0 = g_h0c + (t&1)*BHD;
        const float* sp1 = g_h1c + (((unsigned)(t-1))&1)*BHD;
        // issue all 4 k-chunks as cp.async groups (overlap with dot below)
        #pragma unroll
        for (int c = 0; c < 4; c++){
            const int base = c*4096;
            for (int i = tid; i < 1024; i += 384)
                cpa16(s2u(sh + base + i*4), sp0 + base + i*4);
            if (has_g1)
                for (int i = tid; i < 1024; i += 384)
                    cpa16(s2u(sh + BHD + base + i*4), sp1 + base + i*4);
            asm volatile("cp.async.commit_group;" ::: "memory");
        }

        const bool act = g0u ? (t < TT2) : (t >= 1);
        float s0=0.f, s1=0.f, s2=0.f;
        asm volatile("cp.async.wait_group 3;" ::: "memory"); __syncthreads();
        if (act) dotc(W0, W1, W2, shb_my, b,   0, s0, s1, s2);
        asm volatile("cp.async.wait_group 2;" ::: "memory"); __syncthreads();
        if (act) dotc(W0, W1, W2, shb_my, b, 128, s0, s1, s2);
        asm volatile("cp.async.wait_group 1;" ::: "memory"); __syncthreads();
        if (act) dotc(W0, W1, W2, shb_my, b, 256, s0, s1, s2);
        asm volatile("cp.async.wait_group 0;" ::: "memory"); __syncthreads();
        if (act) dotc(W0, W1, W2, shb_my, b, 384, s0, s1, s2);

        if (!g0u){ sm[warp][0][b] = s0; sm[warp][1][b] = s1; sm[warp][2][b] = s2; }
        __syncthreads();

        if (act){
            if (g0u){
                const float* gi = g_gi0 + ((size_t)t*NB + b)*H3;
                float r = fast_sig (gi[j      ] + s0 + b_hh0[j      ]);
                float z = fast_sig (gi[j+ 512] + s1 + b_hh0[j+ 512]);
                float n = fast_tanh(gi[j+1024] + r*(s2 + b_hh0[j+1024]));
                float hold = sh[CH(b,j)];
                __stcg(&g_h0c[(1-(t&1))*BHD + CH(b,j)], (1.f-z)*n + z*hold);
            } else if (mat == 0){
                const int s = t - 1;
                float xr = s0 + b_ih1[j      ];
                float xz = s1 + b_ih1[j+ 512];
                float xn = s2 + b_ih1[j+1024];
                float hr = sm[warp+1][0][b] + b_hh1[j      ];
                float hz = sm[warp+1][1][b] + b_hh1[j+ 512];
                float hn = sm[warp+1][2][b] + b_hh1[j+1024];
                float r = fast_sig(xr + hr);
                float z = fast_sig(xz + hz);
                float n = fast_tanh(xn + r*hn);
                float h1old = sh[BHD + CH(b,j)];
                float hnew = (1.f-z)*n + z*h1old;
                __stcg(&g_h1c[(t&1)*BHD + CH(b,j)], hnew);
                g_ys[((size_t)s*NB + b)*HD + j] = hnew;
            }
        }
        if (t == TT2) break;
        // ---- two-level grid barrier ----
        __syncthreads();
        if (tid == 0){
            unsigned old;
            asm volatile("atom.acq_rel.gpu.global.add.u32 %0, [%1], %2;"
                         : "=r"(old) : "l"(myc), "r"(1u) : "memory");
            if (old == (unsigned)(t + 1)*16u - 1u){     // last of my 16-block group
                unsigned o2;
                asm volatile("atom.acq_rel.gpu.global.add.u32 %0, [%1], %2;"
                             : "=r"(o2) : "l"(&g_master), "r"(1u) : "memory");
            }
            const unsigned tgt = (unsigned)(t + 1) * 8u;
            unsigned cur;
            do {
                asm volatile("ld.acquire.gpu.global.u32 %0, [%1];"
                             : "=r"(cur) : "l"(&g_master) : "memory");
                if (cur < tgt) __nanosleep(32);
            } while (cur < tgt);
        }
        __syncthreads();
    }
}

// ---------------- final state copy ----------------
__global__ __launch_bounds__(256) void k_fin(float* __restrict__ dout)
{
    int i = blockIdx.x*256 + threadIdx.x;
    if (i >= 2*BHD) return;
    int l = (i >= BHD);
    int r = i & (BHD-1);
    int b = r >> 9, h = r & (HD-1);
    float v = l ? g_h1c[CH(b,h)] : g_h0c[CH(b,h)];
    dout[HF_OFF + i] = v;
}

extern "C" void kernel_launch(void* const* d_in, const int* in_sizes, int n_in,
                              void* d_out, int out_size)
{
    const int*   tok   = (const int*)  d_in[0];
    const float* state = (const float*)d_in[1];
    const float* enc   = (const float*)d_in[2];
    const float* emb   = (const float*)d_in[3];
    const float* wa_W  = (const float*)d_in[4];
    const float* wa_b  = (const float*)d_in[5];
    const float* va_W  = (const float*)d_in[6];
    const float* W_ih0 = (const float*)d_in[7];
    const float* W_hh0 = (const float*)d_in[8];
    const float* b_ih0 = (const float*)d_in[9];
    const float* b_hh0 = (const float*)d_in[10];
    const float* W_ih1 = (const float*)d_in[11];
    const float* W_hh1 = (const float*)d_in[12];
    const float* b_ih1 = (const float*)d_in[13];
    const float* b_hh1 = (const float*)d_in[14];
    const float* out_W = (const float*)d_in[15];
    const float* out_b = (const float*)d_in[16];
    float* dout = (float*)d_out;

    float *pX, *pep, *pq, *pav, *pgi0, *pys;
    __half *pench, *pWxh, *pWeh, *pXh, *pXavh, *pWih0h, *poWh, *pysh;
    cudaGetSymbolAddress((void**)&pX,     g_X);
    cudaGetSymbolAddress((void**)&pep,    g_ep);
    cudaGetSymbolAddress((void**)&pq,     g_q);
    cudaGetSymbolAddress((void**)&pav,    g_av);
    cudaGetSymbolAddress((void**)&pgi0,   g_gi0);
    cudaGetSymbolAddress((void**)&pys,    g_ys);
    cudaGetSymbolAddress((void**)&pench,  h_ench);
    cudaGetSymbolAddress((void**)&pWxh,   h_Wxh);
    cudaGetSymbolAddress((void**)&pWeh,   h_Weh);
    cudaGetSymbolAddress((void**)&pXh,    h_Xh);
    cudaGetSymbolAddress((void**)&pXavh,  h_Xavh);
    cudaGetSymbolAddress((void**)&pWih0h, h_Wih0h);
    cudaGetSymbolAddress((void**)&poWh,   h_oWh);
    cudaGetSymbolAddress((void**)&pysh,   h_ysh);

    cudaFuncSetAttribute(k_rec, cudaFuncAttributeMaxDynamicSharedMemorySize, 2*BHD*4);

    // 1. embed + state init + barrier reset
    k_embed<<<(TT2*NB*HD + 255)/256, 256>>>(tok, emb, state);
    // 2-3. conversions needed by enc_proj
    k_cath<<<TT1*NB, 128>>>(enc,        HD, HD, pench, 1024, 0, 512, 0);   // A2
    k_cath<<<512,    128>>>(wa_W + HD, 2*HD, HD, pWeh, 1024, 0, 512, 1);   // B2
    // 4. enc_proj = enc @ We^T + wa_b   (M=4096, N=512, K'=1024)  << profiled
    k_gemmh<<<dim3(HD/128, (TT1*NB)/128), 256>>>((const uint_t*)pench, 512,
        (const uint_t*)pWeh, 512, wa_b, pep, HD, 1024);
    // 5-6. conversions for q
    k_cath<<<512,    128>>>(wa_W,      2*HD, HD, pWxh, 1024, 0, 512, 1);   // B2
    k_cath<<<TT2*NB, 128>>>(pX,         HD, HD, pXh,  1024, 0, 512, 0);    // A2
    // 7. q = X @ Wx^T                   (M=2048, N=512, K'=1024)
    k_gemmh<<<dim3(HD/128, (TT2*NB)/128), 256>>>((const uint_t*)pXh, 512,
        (const uint_t*)pWxh, 512, nullptr, pq, HD, 1024);

    // remaining conversions
    k_cath<<<H3,     256>>>(W_ih0, 2*HD, 2*HD, pWih0h, 2048, 0, 1024, 1);  // B2
    k_cath<<<VOC,    128>>>(out_W,   HD,   HD, poWh,    512, 0, 0, 2);     // 1-term
    k_cath<<<TT2*NB, 128>>>(pX,      HD,   HD, pXavh,  2048, 0, 1024, 0);  // A2 (X part)

    // attention
    k_att_scores<<<dim3(TT2/8, NB), 256>>>(va_W, dout);
    k_attv<<<dim3(NB, TT2/32, HD/256), 256>>>(enc);
    k_cath<<<TT2*NB, 128>>>(pav, HD, HD, pXavh, 2048, 512, 1536, 0);       // A2 (av part)

    // gi0 = [X, att_v] @ W_ih0^T + b_ih0   (M=2048, N=1536, K'=2048)
    k_gemmh<<<dim3(H3/128, (TT2*NB)/128), 256>>>((const uint_t*)pXavh, 1024,
        (const uint_t*)pWih0h, 1024, b_ih0, pgi0, H3, 2048);

    // recurrence: 128 blocks x 384 threads, 128 KB dynamic smem, single wave
    k_rec<<<NBLK2, 384, 2*BHD*4>>>(W_hh0, b_hh0, W_ih1, b_ih1, W_hh1, b_hh1);

    // y = ys @ out_W^T + out_b   (M=2048, N=32000, K=512, 1-term fp16)
    k_cath<<<TT2*NB, 128>>>(pys, HD, HD, pysh, 512, 0, 0, 2);
    k_gemmh<<<dim3(VOC/128, (TT2*NB)/128), 256>>>((const uint_t*)pysh, 256,
        (const uint_t*)poWh, 256, out_b, dout, VOC, 512);

    // final hidden states
    k_fin<<<(2*BHD + 255)/256, 256>>>(dout);
    (void)in_sizes; (void)n_in; (void)out_size;
}